// round 2
// baseline (speedup 1.0000x reference)
#include <cuda_runtime.h>
#include <cuda_bf16.h>
#include <math.h>

// ---------------- problem constants ----------------
#define Bz   64
#define Sz   32
#define NF   196
#define NP   64
#define ENC  512
#define BENC 768
#define Az   512
#define Dz   512
#define Ez   512
#define Vz   30000
#define KX   2304          // E + ENC + BENC + D = 512+512+768+512
#define G4   2048          // 4*D

// output offsets (floats)
#define OFF_PREDS  0
#define OFF_ALPHA  61440000u   // B*S*V
#define OFF_PA     61841408u   // + B*S*196

// ---------------- scratch (device globals, no allocation) ----------------
__device__ float g_inp0[Bz * 1280];
__device__ float g_u_feat[Bz * NF * Az];      // 25.7 MB
__device__ float g_u_art [Bz * NP * Az];      // 8.4 MB
__device__ float g_h[Bz * Dz], g_c[Bz * Dz];
__device__ float g_ctx[Bz * ENC], g_pctx[Bz * BENC];
__device__ float g_x[Bz * KX];
__device__ float g_gparts[4 * Bz * G4];       // k-split partials
__device__ float g_hall[Sz * Bz * Dz];        // all h_t for deferred fcn

__device__ __forceinline__ float wred(float v) {
#pragma unroll
    for (int o = 16; o; o >>= 1) v += __shfl_xor_sync(0xffffffffu, v, o);
    return v;
}
__device__ __forceinline__ float sigm(float x) { return 1.f / (1.f + expf(-x)); }

// ---------------- mean pooling ----------------
__global__ void mean_kernel(const float* __restrict__ features,
                            const float* __restrict__ articles) {
    int b = blockIdx.x, tid = threadIdx.x;
    for (int k = tid; k < ENC; k += 256) {
        float s = 0.f;
        const float* p = features + (size_t)b * NF * ENC + k;
        for (int n = 0; n < NF; n++) s += p[n * ENC];
        g_inp0[b * 1280 + k] = s * (1.f / NF);
    }
    for (int k = tid; k < BENC; k += 256) {
        float s = 0.f;
        const float* p = articles + (size_t)b * NP * BENC + k;
        for (int n = 0; n < NP; n++) s += p[n * BENC];
        g_inp0[b * 1280 + ENC + k] = s * (1.f / NP);
    }
}

// ---------------- init h0/c0 ----------------
__global__ void init_hc(const float* __restrict__ hw, const float* __restrict__ hb,
                        const float* __restrict__ cw, const float* __restrict__ cb) {
    int b = blockIdx.x, tid = threadIdx.x;
    int lane = tid & 31, wid = tid >> 5;
    __shared__ float x[1280];
    for (int k = tid; k < 1280; k += 256) x[k] = g_inp0[b * 1280 + k];
    __syncthreads();
    for (int d = wid; d < Dz; d += 8) {
        float sh = 0.f, sc = 0.f;
        const float* hr = hw + (size_t)d * 1280;
        const float* cr = cw + (size_t)d * 1280;
        for (int k = lane; k < 1280; k += 32) { float xv = x[k]; sh += hr[k] * xv; sc += cr[k] * xv; }
#pragma unroll
        for (int o = 16; o; o >>= 1) {
            sh += __shfl_xor_sync(0xffffffffu, sh, o);
            sc += __shfl_xor_sync(0xffffffffu, sc, o);
        }
        if (!lane) { g_h[b * Dz + d] = sh + hb[d]; g_c[b * Dz + d] = sc + cb[d]; }
    }
}

// ---------------- generic SGEMM: C[M,N] = A[M,K] @ W[N,K]^T + bias ----------------
// BM=128 BN=64 BK=16, 256 threads, 8x4 per thread. M must be multiple of 128, K of 16.
template <bool PERM>
__global__ void sgemm128x64(const float* __restrict__ A, const float* __restrict__ W,
                            const float* __restrict__ bias, float* __restrict__ C,
                            int M, int N, int K) {
    __shared__ float As[16][128];
    __shared__ float Bs[16][64];
    const int m0 = blockIdx.x * 128, n0 = blockIdx.y * 64;
    const int tid = threadIdx.x;
    const int tx = tid % 16, ty = tid / 16;
    const int ar = tid / 4, ac = (tid % 4) * 4;   // A rows ar, ar+64
    float acc[8][4] = {};
    for (int k0 = 0; k0 < K; k0 += 16) {
        float4 a0 = *(const float4*)&A[(size_t)(m0 + ar) * K + k0 + ac];
        float4 a1 = *(const float4*)&A[(size_t)(m0 + ar + 64) * K + k0 + ac];
        float4 b0 = make_float4(0.f, 0.f, 0.f, 0.f);
        if (n0 + ar < N) b0 = *(const float4*)&W[(size_t)(n0 + ar) * K + k0 + ac];
        __syncthreads();
        As[ac + 0][ar] = a0.x; As[ac + 1][ar] = a0.y; As[ac + 2][ar] = a0.z; As[ac + 3][ar] = a0.w;
        As[ac + 0][ar + 64] = a1.x; As[ac + 1][ar + 64] = a1.y; As[ac + 2][ar + 64] = a1.z; As[ac + 3][ar + 64] = a1.w;
        Bs[ac + 0][ar] = b0.x; Bs[ac + 1][ar] = b0.y; Bs[ac + 2][ar] = b0.z; Bs[ac + 3][ar] = b0.w;
        __syncthreads();
#pragma unroll
        for (int k = 0; k < 16; k++) {
            float ra[8], rb[4];
            *(float4*)&ra[0] = *(const float4*)&As[k][ty * 8];
            *(float4*)&ra[4] = *(const float4*)&As[k][ty * 8 + 4];
            *(float4*)&rb[0] = *(const float4*)&Bs[k][tx * 4];
#pragma unroll
            for (int i = 0; i < 8; i++)
#pragma unroll
                for (int j = 0; j < 4; j++) acc[i][j] += ra[i] * rb[j];
        }
    }
#pragma unroll
    for (int i = 0; i < 8; i++) {
        int m = m0 + ty * 8 + i;
#pragma unroll
        for (int j = 0; j < 4; j++) {
            int n = n0 + tx * 4 + j;
            if (n < N) {
                float v = acc[i][j] + bias[n];
                if (PERM) {
                    int bb = m & 63, tt = m >> 6;           // m = t*64 + b
                    C[(size_t)(bb * Sz + tt) * N + n] = v;  // preds[b][t][v]
                } else {
                    C[(size_t)m * N + n] = v;
                }
            }
        }
    }
}

// ---------------- fused attention (one block per (type, batch)) ----------------
__global__ void attend_kernel(const float* __restrict__ features, const float* __restrict__ articles,
                              const float* __restrict__ attWw, const float* __restrict__ attWb,
                              const float* __restrict__ attAw, const float* __restrict__ attAb,
                              const float* __restrict__ paWw, const float* __restrict__ paWb,
                              const float* __restrict__ paAw, const float* __restrict__ paAb,
                              float* __restrict__ out, int t) {
    const int type = blockIdx.x, b = blockIdx.y;
    const int tid = threadIdx.x, lane = tid & 31, wid = tid >> 5;
    __shared__ float hsh[512], wah[512], sc[200];
    __shared__ float red[8];
    __shared__ float s_max, s_sum;

    const float* Ww = type ? paWw : attWw;
    const float* Wb = type ? paWb : attWb;
    const float* Aw = type ? paAw : attAw;
    const float  Ab = (type ? paAb : attAb)[0];
    const float* u  = type ? (g_u_art + (size_t)b * NP * Az) : (g_u_feat + (size_t)b * NF * Az);
    const float* F  = type ? (articles + (size_t)b * NP * BENC) : (features + (size_t)b * NF * ENC);
    const int Nn = type ? NP : NF;
    const int Kd = type ? BENC : ENC;
    float* ctxp = type ? (g_pctx + b * BENC) : (g_ctx + b * ENC);

    hsh[tid] = g_h[b * Dz + tid];
    hsh[tid + 256] = g_h[b * Dz + tid + 256];
    __syncthreads();

    // w_ah = h @ Ww^T + Wb
    for (int a = wid; a < Az; a += 8) {
        float s = 0.f;
        const float* wr_ = Ww + (size_t)a * Dz;
        for (int k = lane; k < Dz; k += 32) s += wr_[k] * hsh[k];
        s = wred(s);
        if (!lane) wah[a] = s + Wb[a];
    }
    __syncthreads();

    // scores[n] = tanh(u[n] + w_ah) . Aw + Ab
    for (int n = wid; n < Nn; n += 8) {
        const float* ur = u + (size_t)n * Az;
        float s = 0.f;
        for (int a = lane; a < Az; a += 32) s += tanhf(ur[a] + wah[a]) * Aw[a];
        s = wred(s);
        if (!lane) sc[n] = s + Ab;
    }
    __syncthreads();

    // softmax over n
    float m = -1e30f;
    for (int n = tid; n < Nn; n += 256) m = fmaxf(m, sc[n]);
#pragma unroll
    for (int o = 16; o; o >>= 1) m = fmaxf(m, __shfl_xor_sync(0xffffffffu, m, o));
    if (!lane) red[wid] = m;
    __syncthreads();
    if (tid == 0) {
        float mm = red[0];
        for (int i = 1; i < 8; i++) mm = fmaxf(mm, red[i]);
        s_max = mm;
    }
    __syncthreads();
    float e = 0.f;
    for (int n = tid; n < Nn; n += 256) { float ex = expf(sc[n] - s_max); sc[n] = ex; e += ex; }
    e = wred(e);
    if (!lane) red[wid] = e;
    __syncthreads();
    if (tid == 0) {
        float ss = 0.f;
        for (int i = 0; i < 8; i++) ss += red[i];
        s_sum = ss;
    }
    __syncthreads();
    const float inv = 1.f / s_sum;
    size_t obase = type ? ((size_t)OFF_PA + (size_t)(b * Sz + t) * NP)
                        : ((size_t)OFF_ALPHA + (size_t)(b * Sz + t) * NF);
    for (int n = tid; n < Nn; n += 256) { float al = sc[n] * inv; sc[n] = al; out[obase + n] = al; }
    __syncthreads();

    // ctx = alpha @ F
    for (int k = tid; k < Kd; k += 256) {
        float acc = 0.f;
        for (int n = 0; n < Nn; n++) acc += sc[n] * F[(size_t)n * Kd + k];
        ctxp[k] = acc;
    }
}

// ---------------- build x = [emb_t, ctx, pctx, h] ----------------
__global__ void build_x(const float* __restrict__ emb, const int* __restrict__ captions, int t) {
    int b = blockIdx.x, tid = threadIdx.x;
    int cap = captions[b * Sz + t];
    const float* e = emb + (size_t)cap * Ez;
    float* x = g_x + b * KX;
    for (int k = tid; k < 512; k += 256) x[k] = e[k];
    for (int k = tid; k < 512; k += 256) x[512 + k] = g_ctx[b * ENC + k];
    for (int k = tid; k < 768; k += 256) x[1024 + k] = g_pctx[b * BENC + k];
    for (int k = tid; k < 512; k += 256) x[1792 + k] = g_h[b * Dz + k];
}

// ---------------- LSTM gates GEMM (M=64, N=2048, K=2304), K-split x4 ----------------
__global__ void gates_gemm(const float* __restrict__ w_ih, const float* __restrict__ w_hh) {
    // grid (64 col-blocks of 32, 4 K-splits), 256 threads
    __shared__ float Xs[16][64];
    __shared__ float Ws[16][32];
    const int n0 = blockIdx.x * 32;
    const int kbase = blockIdx.y * 576;
    const int tid = threadIdx.x;
    const int tx = tid % 8, ty = tid / 8;   // ty*2 rows (batch), tx*4 cols
    float acc[2][4] = {};
    const int xr = tid / 4, xc = (tid % 4) * 4;
    for (int it = 0; it < 36; it++) {
        int k0 = kbase + it * 16;
        float4 xv = *(const float4*)&g_x[xr * KX + k0 + xc];
        float4 wv = make_float4(0.f, 0.f, 0.f, 0.f);
        if (tid < 128) {
            int j = n0 + tid / 4;
            int kg = k0 + (tid % 4) * 4;
            const float* src = (kg < 1792) ? &w_ih[(size_t)j * 1792 + kg]
                                           : &w_hh[(size_t)j * 512 + (kg - 1792)];
            wv = *(const float4*)src;
        }
        __syncthreads();
        Xs[xc + 0][xr] = xv.x; Xs[xc + 1][xr] = xv.y; Xs[xc + 2][xr] = xv.z; Xs[xc + 3][xr] = xv.w;
        if (tid < 128) {
            int n = tid / 4, kq = (tid % 4) * 4;
            Ws[kq + 0][n] = wv.x; Ws[kq + 1][n] = wv.y; Ws[kq + 2][n] = wv.z; Ws[kq + 3][n] = wv.w;
        }
        __syncthreads();
#pragma unroll
        for (int k = 0; k < 16; k++) {
            float ra0 = Xs[k][ty * 2], ra1 = Xs[k][ty * 2 + 1];
            float rb[4];
            *(float4*)&rb[0] = *(const float4*)&Ws[k][tx * 4];
#pragma unroll
            for (int j = 0; j < 4; j++) { acc[0][j] += ra0 * rb[j]; acc[1][j] += ra1 * rb[j]; }
        }
    }
#pragma unroll
    for (int i = 0; i < 2; i++) {
        int b = ty * 2 + i;
#pragma unroll
        for (int j = 0; j < 4; j++) {
            int n = n0 + tx * 4 + j;
            g_gparts[((size_t)blockIdx.y * Bz + b) * G4 + n] = acc[i][j];
        }
    }
}

// ---------------- LSTM pointwise update ----------------
__global__ void lstm_update(const float* __restrict__ b_ih, const float* __restrict__ b_hh, int t) {
    int b = blockIdx.x, tid = threadIdx.x;
    for (int d = tid; d < Dz; d += 256) {
        float gi = b_ih[d] + b_hh[d];
        float gf = b_ih[512 + d] + b_hh[512 + d];
        float gg = b_ih[1024 + d] + b_hh[1024 + d];
        float go = b_ih[1536 + d] + b_hh[1536 + d];
#pragma unroll
        for (int ks = 0; ks < 4; ks++) {
            const float* gp = g_gparts + ((size_t)ks * Bz + b) * G4;
            gi += gp[d]; gf += gp[512 + d]; gg += gp[1024 + d]; go += gp[1536 + d];
        }
        float cp = g_c[b * Dz + d];
        float cn = sigm(gf) * cp + sigm(gi) * tanhf(gg);
        float hn = sigm(go) * tanhf(cn);
        g_c[b * Dz + d] = cn;
        g_h[b * Dz + d] = hn;
        g_hall[((size_t)t * Bz + b) * Dz + d] = hn;
    }
}

// ---------------- launcher ----------------
extern "C" void kernel_launch(void* const* d_in, const int* in_sizes, int n_in,
                              void* d_out, int out_size) {
    const float* features = (const float*)d_in[0];
    const float* articles = (const float*)d_in[1];
    const int*   captions = (const int*)d_in[2];
    const float* emb      = (const float*)d_in[3];
    const float* att_W_w  = (const float*)d_in[4];
    const float* att_W_b  = (const float*)d_in[5];
    const float* att_U_w  = (const float*)d_in[6];
    const float* att_U_b  = (const float*)d_in[7];
    const float* att_A_w  = (const float*)d_in[8];
    const float* att_A_b  = (const float*)d_in[9];
    const float* pa_W_w   = (const float*)d_in[10];
    const float* pa_W_b   = (const float*)d_in[11];
    const float* pa_U_w   = (const float*)d_in[12];
    const float* pa_U_b   = (const float*)d_in[13];
    const float* pa_A_w   = (const float*)d_in[14];
    const float* pa_A_b   = (const float*)d_in[15];
    const float* init_h_w = (const float*)d_in[16];
    const float* init_h_b = (const float*)d_in[17];
    const float* init_c_w = (const float*)d_in[18];
    const float* init_c_b = (const float*)d_in[19];
    const float* lstm_w_ih = (const float*)d_in[20];
    const float* lstm_w_hh = (const float*)d_in[21];
    const float* lstm_b_ih = (const float*)d_in[22];
    const float* lstm_b_hh = (const float*)d_in[23];
    const float* fcn_w    = (const float*)d_in[24];
    const float* fcn_b    = (const float*)d_in[25];
    float* out = (float*)d_out;

    float *p_uf, *p_ua, *p_hall;
    cudaGetSymbolAddress((void**)&p_uf, g_u_feat);
    cudaGetSymbolAddress((void**)&p_ua, g_u_art);
    cudaGetSymbolAddress((void**)&p_hall, g_hall);

    mean_kernel<<<Bz, 256>>>(features, articles);
    init_hc<<<Bz, 256>>>(init_h_w, init_h_b, init_c_w, init_c_b);

    // u_feat = features @ att_U_w^T + b : [12544,512]
    sgemm128x64<false><<<dim3(98, 8), 256>>>(features, att_U_w, att_U_b, p_uf, Bz * NF, Az, ENC);
    // u_art = articles @ pa_U_w^T + b : [4096,512]
    sgemm128x64<false><<<dim3(32, 8), 256>>>(articles, pa_U_w, pa_U_b, p_ua, Bz * NP, Az, BENC);

    for (int t = 0; t < Sz; t++) {
        attend_kernel<<<dim3(2, Bz), 256>>>(features, articles,
                                            att_W_w, att_W_b, att_A_w, att_A_b,
                                            pa_W_w, pa_W_b, pa_A_w, pa_A_b, out, t);
        build_x<<<Bz, 256>>>(emb, captions, t);
        gates_gemm<<<dim3(64, 4), 256>>>(lstm_w_ih, lstm_w_hh);
        lstm_update<<<Bz, 256>>>(lstm_b_ih, lstm_b_hh, t);
    }

    // preds: [2048,512] @ [30000,512]^T, permuted store into [B,S,V]
    sgemm128x64<true><<<dim3(16, 469), 256>>>(p_hall, fcn_w, fcn_b, out, Sz * Bz, Vz, Dz);
}

// round 3
// speedup vs baseline: 1.2842x; 1.2842x over previous
#include <cuda_runtime.h>
#include <cuda_bf16.h>
#include <math.h>

// ---------------- problem constants ----------------
#define Bz   64
#define Sz   32
#define NF   196
#define NP   64
#define ENC  512
#define BENC 768
#define Az   512
#define Dz   512
#define Ez   512
#define Vz   30000
#define G4   2048          // 4*D

// output offsets (floats)
#define OFF_ALPHA  61440000u   // B*S*V
#define OFF_PA     61841408u   // + B*S*196

// ---------------- scratch (device globals, no allocation) ----------------
__device__ float g_inp0[Bz * 1280];
__device__ float g_u_feat[Bz * NF * Az];      // 25.7 MB
__device__ float g_u_art [Bz * NP * Az];      // 8.4 MB
__device__ float g_h[Bz * Dz], g_c[Bz * Dz];
__device__ float g_ctx[Bz * ENC], g_pctx[Bz * BENC];
__device__ float g_embs[Bz * Sz * Ez];        // all embeddings, 4 MB
__device__ float g_gparts[4 * Bz * G4];       // k-split partials
__device__ float g_hall[Sz * Bz * Dz];        // all h_t for deferred fcn

__device__ __forceinline__ float wred(float v) {
#pragma unroll
    for (int o = 16; o; o >>= 1) v += __shfl_xor_sync(0xffffffffu, v, o);
    return v;
}
__device__ __forceinline__ float sigm(float x) { return 1.f / (1.f + expf(-x)); }
__device__ __forceinline__ float tanha(float x) {
    float y; asm("tanh.approx.f32 %0, %1;" : "=f"(y) : "f"(x)); return y;
}

// ---------------- mean pooling ----------------
__global__ void mean_kernel(const float* __restrict__ features,
                            const float* __restrict__ articles) {
    int b = blockIdx.x, tid = threadIdx.x;
    for (int k = tid; k < ENC; k += 256) {
        float s = 0.f;
        const float* p = features + (size_t)b * NF * ENC + k;
        for (int n = 0; n < NF; n++) s += p[n * ENC];
        g_inp0[b * 1280 + k] = s * (1.f / NF);
    }
    for (int k = tid; k < BENC; k += 256) {
        float s = 0.f;
        const float* p = articles + (size_t)b * NP * BENC + k;
        for (int n = 0; n < NP; n++) s += p[n * BENC];
        g_inp0[b * 1280 + ENC + k] = s * (1.f / NP);
    }
}

// ---------------- init h0/c0 ----------------
__global__ void init_hc(const float* __restrict__ hw, const float* __restrict__ hb,
                        const float* __restrict__ cw, const float* __restrict__ cb) {
    int b = blockIdx.x, tid = threadIdx.x;
    int lane = tid & 31, wid = tid >> 5;
    __shared__ float x[1280];
    for (int k = tid; k < 1280; k += 256) x[k] = g_inp0[b * 1280 + k];
    __syncthreads();
    for (int d = wid; d < Dz; d += 8) {
        float sh = 0.f, sc = 0.f;
        const float* hr = hw + (size_t)d * 1280;
        const float* cr = cw + (size_t)d * 1280;
        for (int k = lane; k < 1280; k += 32) { float xv = x[k]; sh += hr[k] * xv; sc += cr[k] * xv; }
#pragma unroll
        for (int o = 16; o; o >>= 1) {
            sh += __shfl_xor_sync(0xffffffffu, sh, o);
            sc += __shfl_xor_sync(0xffffffffu, sc, o);
        }
        if (!lane) { g_h[b * Dz + d] = sh + hb[d]; g_c[b * Dz + d] = sc + cb[d]; }
    }
}

// ---------------- embed all captions once ----------------
__global__ void embed_all(const float* __restrict__ emb, const int* __restrict__ captions) {
    int bs = blockIdx.x;          // b*Sz + t
    int cap = captions[bs];
    const float* e = emb + (size_t)cap * Ez;
    for (int k = threadIdx.x; k < Ez; k += 256) g_embs[(size_t)bs * Ez + k] = e[k];
}

// ---------------- SGEMM: C[M,N] = A[M,K] @ W[N,K]^T + bias ----------------
// BM=128 BN=128 BK=16, 256 threads, 8x8 per thread, register prefetch.
// M % 128 == 0, K % 16 == 0; N guarded.
template <bool PERM>
__global__ void __launch_bounds__(256, 2)
sgemm128x128(const float* __restrict__ A, const float* __restrict__ W,
             const float* __restrict__ bias, float* __restrict__ C,
             int M, int N, int K) {
    __shared__ float As[16][128];
    __shared__ float Bs[16][128];
    const int m0 = blockIdx.x * 128, n0 = blockIdx.y * 128;
    const int tid = threadIdx.x;
    const int tx = tid & 15, ty = tid >> 4;
    const int lr = tid >> 2, lc = (tid & 3) << 2;
    const float4 z4 = make_float4(0.f, 0.f, 0.f, 0.f);

    float4 a0, a1, b0, b1;
    a0 = *(const float4*)&A[(size_t)(m0 + lr) * K + lc];
    a1 = *(const float4*)&A[(size_t)(m0 + lr + 64) * K + lc];
    b0 = (n0 + lr < N) ? *(const float4*)&W[(size_t)(n0 + lr) * K + lc] : z4;
    b1 = (n0 + lr + 64 < N) ? *(const float4*)&W[(size_t)(n0 + lr + 64) * K + lc] : z4;

    float acc[8][8] = {};
    for (int k0 = 0; k0 < K; k0 += 16) {
        As[lc + 0][lr] = a0.x; As[lc + 1][lr] = a0.y; As[lc + 2][lr] = a0.z; As[lc + 3][lr] = a0.w;
        As[lc + 0][lr + 64] = a1.x; As[lc + 1][lr + 64] = a1.y; As[lc + 2][lr + 64] = a1.z; As[lc + 3][lr + 64] = a1.w;
        Bs[lc + 0][lr] = b0.x; Bs[lc + 1][lr] = b0.y; Bs[lc + 2][lr] = b0.z; Bs[lc + 3][lr] = b0.w;
        Bs[lc + 0][lr + 64] = b1.x; Bs[lc + 1][lr + 64] = b1.y; Bs[lc + 2][lr + 64] = b1.z; Bs[lc + 3][lr + 64] = b1.w;
        __syncthreads();
        if (k0 + 16 < K) {
            int kn = k0 + 16;
            a0 = *(const float4*)&A[(size_t)(m0 + lr) * K + kn + lc];
            a1 = *(const float4*)&A[(size_t)(m0 + lr + 64) * K + kn + lc];
            b0 = (n0 + lr < N) ? *(const float4*)&W[(size_t)(n0 + lr) * K + kn + lc] : z4;
            b1 = (n0 + lr + 64 < N) ? *(const float4*)&W[(size_t)(n0 + lr + 64) * K + kn + lc] : z4;
        }
#pragma unroll
        for (int k = 0; k < 16; k++) {
            float ra[8], rb[8];
            *(float4*)&ra[0] = *(const float4*)&As[k][ty * 8];
            *(float4*)&ra[4] = *(const float4*)&As[k][ty * 8 + 4];
            *(float4*)&rb[0] = *(const float4*)&Bs[k][tx * 8];
            *(float4*)&rb[4] = *(const float4*)&Bs[k][tx * 8 + 4];
#pragma unroll
            for (int i = 0; i < 8; i++)
#pragma unroll
                for (int j = 0; j < 8; j++) acc[i][j] += ra[i] * rb[j];
        }
        __syncthreads();
    }
#pragma unroll
    for (int i = 0; i < 8; i++) {
        int m = m0 + ty * 8 + i;
#pragma unroll
        for (int j = 0; j < 8; j++) {
            int n = n0 + tx * 8 + j;
            if (n < N) {
                float v = acc[i][j] + bias[n];
                if (PERM) {
                    int bb = m & 63, tt = m >> 6;            // m = t*64 + b
                    C[(size_t)(bb * Sz + tt) * N + n] = v;   // preds[b][t][v]
                } else {
                    C[(size_t)m * N + n] = v;
                }
            }
        }
    }
}

// ---------------- fused attention (one block per (type, batch)) ----------------
__global__ void attend_kernel(const float* __restrict__ features, const float* __restrict__ articles,
                              const float* __restrict__ attWw, const float* __restrict__ attWb,
                              const float* __restrict__ attAw, const float* __restrict__ attAb,
                              const float* __restrict__ paWw, const float* __restrict__ paWb,
                              const float* __restrict__ paAw, const float* __restrict__ paAb,
                              float* __restrict__ out, int t) {
    const int type = blockIdx.x, b = blockIdx.y;
    const int tid = threadIdx.x, lane = tid & 31, wid = tid >> 5;
    __shared__ float hsh[512], wah[512], sc[200];
    __shared__ float red[8];
    __shared__ float s_max, s_sum;

    const float* Ww = type ? paWw : attWw;
    const float* Wb = type ? paWb : attWb;
    const float* Aw = type ? paAw : attAw;
    const float  Ab = (type ? paAb : attAb)[0];
    const float* u  = type ? (g_u_art + (size_t)b * NP * Az) : (g_u_feat + (size_t)b * NF * Az);
    const float* F  = type ? (articles + (size_t)b * NP * BENC) : (features + (size_t)b * NF * ENC);
    const int Nn = type ? NP : NF;
    const int Kd = type ? BENC : ENC;
    float* ctxp = type ? (g_pctx + b * BENC) : (g_ctx + b * ENC);

    hsh[tid] = g_h[b * Dz + tid];
    hsh[tid + 256] = g_h[b * Dz + tid + 256];
    __syncthreads();

    // w_ah = h @ Ww^T + Wb
    for (int a = wid; a < Az; a += 8) {
        float s = 0.f;
        const float* wr_ = Ww + (size_t)a * Dz;
        for (int k = lane; k < Dz; k += 32) s += wr_[k] * hsh[k];
        s = wred(s);
        if (!lane) wah[a] = s + Wb[a];
    }
    __syncthreads();

    // scores[n] = tanh(u[n] + w_ah) . Aw + Ab   (MUFU tanh)
    for (int n = wid; n < Nn; n += 8) {
        const float* ur = u + (size_t)n * Az;
        float s = 0.f;
        for (int a = lane; a < Az; a += 32) s += tanha(ur[a] + wah[a]) * Aw[a];
        s = wred(s);
        if (!lane) sc[n] = s + Ab;
    }
    __syncthreads();

    // softmax over n
    float m = -1e30f;
    for (int n = tid; n < Nn; n += 256) m = fmaxf(m, sc[n]);
#pragma unroll
    for (int o = 16; o; o >>= 1) m = fmaxf(m, __shfl_xor_sync(0xffffffffu, m, o));
    if (!lane) red[wid] = m;
    __syncthreads();
    if (tid == 0) {
        float mm = red[0];
        for (int i = 1; i < 8; i++) mm = fmaxf(mm, red[i]);
        s_max = mm;
    }
    __syncthreads();
    float e = 0.f;
    for (int n = tid; n < Nn; n += 256) { float ex = expf(sc[n] - s_max); sc[n] = ex; e += ex; }
    e = wred(e);
    if (!lane) red[wid] = e;
    __syncthreads();
    if (tid == 0) {
        float ss = 0.f;
        for (int i = 0; i < 8; i++) ss += red[i];
        s_sum = ss;
    }
    __syncthreads();
    const float inv = 1.f / s_sum;
    size_t obase = type ? ((size_t)OFF_PA + (size_t)(b * Sz + t) * NP)
                        : ((size_t)OFF_ALPHA + (size_t)(b * Sz + t) * NF);
    for (int n = tid; n < Nn; n += 256) { float al = sc[n] * inv; sc[n] = al; out[obase + n] = al; }
    __syncthreads();

    // ctx = alpha @ F
    for (int k = tid; k < Kd; k += 256) {
        float acc = 0.f;
        for (int n = 0; n < Nn; n++) acc += sc[n] * F[(size_t)n * Kd + k];
        ctxp[k] = acc;
    }
}

// ---------------- LSTM gates GEMM, split by x-segment ----------------
// grid (64 n-blocks of 32, 4 segments), 256 threads
__global__ void gates_gemm(const float* __restrict__ w_ih, const float* __restrict__ w_hh, int t) {
    __shared__ float Xs[16][64];
    __shared__ float Ws[16][32];
    const int n0 = blockIdx.x * 32;
    const int s  = blockIdx.y;
    const int tid = threadIdx.x;
    const int tx = tid % 8, ty = tid / 8;   // ty*2 rows (batch), tx*4 cols
    const int xr = tid / 4, xc = (tid % 4) * 4;

    const float* xs;
    int Ks, kofs;
    if (s == 0)      { xs = g_embs + ((size_t)xr * Sz + t) * Ez; Ks = 512; kofs = 0; }
    else if (s == 1) { xs = g_ctx + xr * ENC;  Ks = 512; kofs = 512; }
    else if (s == 2) { xs = g_pctx + xr * BENC; Ks = 768; kofs = 1024; }
    else             { xs = g_h + xr * Dz;     Ks = 512; kofs = 0; }   // w_hh

    const int iters = Ks / 16;
    float acc[2][4] = {};
    for (int it = 0; it < iters; it++) {
        int kl = it * 16;
        float4 xv = *(const float4*)&xs[kl + xc];
        float4 wv = make_float4(0.f, 0.f, 0.f, 0.f);
        if (tid < 128) {
            int j = n0 + tid / 4;
            int kg = kl + (tid % 4) * 4;
            const float* src = (s == 3) ? &w_hh[(size_t)j * 512 + kg]
                                        : &w_ih[(size_t)j * 1792 + kofs + kg];
            wv = *(const float4*)src;
        }
        __syncthreads();
        Xs[xc + 0][xr] = xv.x; Xs[xc + 1][xr] = xv.y; Xs[xc + 2][xr] = xv.z; Xs[xc + 3][xr] = xv.w;
        if (tid < 128) {
            int n = tid / 4, kq = (tid % 4) * 4;
            Ws[kq + 0][n] = wv.x; Ws[kq + 1][n] = wv.y; Ws[kq + 2][n] = wv.z; Ws[kq + 3][n] = wv.w;
        }
        __syncthreads();
#pragma unroll
        for (int k = 0; k < 16; k++) {
            float ra0 = Xs[k][ty * 2], ra1 = Xs[k][ty * 2 + 1];
            float rb[4];
            *(float4*)&rb[0] = *(const float4*)&Ws[k][tx * 4];
#pragma unroll
            for (int j = 0; j < 4; j++) { acc[0][j] += ra0 * rb[j]; acc[1][j] += ra1 * rb[j]; }
        }
        __syncthreads();
    }
#pragma unroll
    for (int i = 0; i < 2; i++) {
        int b = ty * 2 + i;
#pragma unroll
        for (int j = 0; j < 4; j++) {
            int n = n0 + tx * 4 + j;
            g_gparts[((size_t)s * Bz + b) * G4 + n] = acc[i][j];
        }
    }
}

// ---------------- LSTM pointwise update ----------------
__global__ void lstm_update(const float* __restrict__ b_ih, const float* __restrict__ b_hh, int t) {
    int b = blockIdx.x, tid = threadIdx.x;
    for (int d = tid; d < Dz; d += 256) {
        float gi = b_ih[d] + b_hh[d];
        float gf = b_ih[512 + d] + b_hh[512 + d];
        float gg = b_ih[1024 + d] + b_hh[1024 + d];
        float go = b_ih[1536 + d] + b_hh[1536 + d];
#pragma unroll
        for (int ks = 0; ks < 4; ks++) {
            const float* gp = g_gparts + ((size_t)ks * Bz + b) * G4;
            gi += gp[d]; gf += gp[512 + d]; gg += gp[1024 + d]; go += gp[1536 + d];
        }
        float cp = g_c[b * Dz + d];
        float cn = sigm(gf) * cp + sigm(gi) * tanhf(gg);
        float hn = sigm(go) * tanhf(cn);
        g_c[b * Dz + d] = cn;
        g_h[b * Dz + d] = hn;
        g_hall[((size_t)t * Bz + b) * Dz + d] = hn;
    }
}

// ---------------- launcher ----------------
extern "C" void kernel_launch(void* const* d_in, const int* in_sizes, int n_in,
                              void* d_out, int out_size) {
    const float* features = (const float*)d_in[0];
    const float* articles = (const float*)d_in[1];
    const int*   captions = (const int*)d_in[2];
    const float* emb      = (const float*)d_in[3];
    const float* att_W_w  = (const float*)d_in[4];
    const float* att_W_b  = (const float*)d_in[5];
    const float* att_U_w  = (const float*)d_in[6];
    const float* att_U_b  = (const float*)d_in[7];
    const float* att_A_w  = (const float*)d_in[8];
    const float* att_A_b  = (const float*)d_in[9];
    const float* pa_W_w   = (const float*)d_in[10];
    const float* pa_W_b   = (const float*)d_in[11];
    const float* pa_U_w   = (const float*)d_in[12];
    const float* pa_U_b   = (const float*)d_in[13];
    const float* pa_A_w   = (const float*)d_in[14];
    const float* pa_A_b   = (const float*)d_in[15];
    const float* init_h_w = (const float*)d_in[16];
    const float* init_h_b = (const float*)d_in[17];
    const float* init_c_w = (const float*)d_in[18];
    const float* init_c_b = (const float*)d_in[19];
    const float* lstm_w_ih = (const float*)d_in[20];
    const float* lstm_w_hh = (const float*)d_in[21];
    const float* lstm_b_ih = (const float*)d_in[22];
    const float* lstm_b_hh = (const float*)d_in[23];
    const float* fcn_w    = (const float*)d_in[24];
    const float* fcn_b    = (const float*)d_in[25];
    float* out = (float*)d_out;

    float *p_uf, *p_ua, *p_hall;
    cudaGetSymbolAddress((void**)&p_uf, g_u_feat);
    cudaGetSymbolAddress((void**)&p_ua, g_u_art);
    cudaGetSymbolAddress((void**)&p_hall, g_hall);

    mean_kernel<<<Bz, 256>>>(features, articles);
    init_hc<<<Bz, 256>>>(init_h_w, init_h_b, init_c_w, init_c_b);
    embed_all<<<Bz * Sz, 256>>>(emb, captions);

    // u_feat = features @ att_U_w^T + b : [12544,512]
    sgemm128x128<false><<<dim3(98, 4), 256>>>(features, att_U_w, att_U_b, p_uf, Bz * NF, Az, ENC);
    // u_art = articles @ pa_U_w^T + b : [4096,512]
    sgemm128x128<false><<<dim3(32, 4), 256>>>(articles, pa_U_w, pa_U_b, p_ua, Bz * NP, Az, BENC);

    for (int t = 0; t < Sz; t++) {
        attend_kernel<<<dim3(2, Bz), 256>>>(features, articles,
                                            att_W_w, att_W_b, att_A_w, att_A_b,
                                            pa_W_w, pa_W_b, pa_A_w, pa_A_b, out, t);
        gates_gemm<<<dim3(64, 4), 256>>>(lstm_w_ih, lstm_w_hh, t);
        lstm_update<<<Bz, 256>>>(lstm_b_ih, lstm_b_hh, t);
    }

    // preds: [2048,512] @ [30000,512]^T, permuted store into [B,S,V]
    sgemm128x128<true><<<dim3(16, 235), 256>>>(p_hall, fcn_w, fcn_b, out, Sz * Bz, Vz, Dz);
}

// round 4
// speedup vs baseline: 1.2919x; 1.0060x over previous
#include <cuda_runtime.h>
#include <cuda_bf16.h>
#include <math.h>

// ---------------- problem constants ----------------
#define Bz   64
#define Sz   32
#define NF   196
#define NP   64
#define ENC  512
#define BENC 768
#define Az   512
#define Dz   512
#define Ez   512
#define Vz   30000
#define G4   2048          // 4*D

// output offsets (floats)
#define OFF_ALPHA  61440000u   // B*S*V
#define OFF_PA     61841408u   // + B*S*196

// ---------------- scratch (device globals, no allocation) ----------------
__device__ float g_inp0[Bz * 1280];
__device__ float g_u_feat[Bz * NF * Az];      // 25.7 MB
__device__ float g_u_art [Bz * NP * Az];      // 8.4 MB
__device__ float g_h[Bz * Dz], g_c[Bz * Dz];
__device__ float g_ctx[Bz * ENC], g_pctx[Bz * BENC];
__device__ float g_embs[Bz * Sz * Ez];        // all embeddings, 4 MB
__device__ float g_gparts[4 * Bz * G4];       // k-split partials
__device__ float g_hall[Sz * Bz * Dz];        // all h_t for deferred fcn

__device__ __forceinline__ float wred(float v) {
#pragma unroll
    for (int o = 16; o; o >>= 1) v += __shfl_xor_sync(0xffffffffu, v, o);
    return v;
}
__device__ __forceinline__ float sigm(float x) { return 1.f / (1.f + expf(-x)); }
__device__ __forceinline__ float tanha(float x) {
    float y; asm("tanh.approx.f32 %0, %1;" : "=f"(y) : "f"(x)); return y;
}

// ---------------- mean pooling ----------------
__global__ void mean_kernel(const float* __restrict__ features,
                            const float* __restrict__ articles) {
    int b = blockIdx.x, tid = threadIdx.x;
    for (int k = tid; k < ENC; k += 256) {
        float s = 0.f;
        const float* p = features + (size_t)b * NF * ENC + k;
        for (int n = 0; n < NF; n++) s += p[n * ENC];
        g_inp0[b * 1280 + k] = s * (1.f / NF);
    }
    for (int k = tid; k < BENC; k += 256) {
        float s = 0.f;
        const float* p = articles + (size_t)b * NP * BENC + k;
        for (int n = 0; n < NP; n++) s += p[n * BENC];
        g_inp0[b * 1280 + ENC + k] = s * (1.f / NP);
    }
}

// ---------------- init h0/c0 ----------------
__global__ void init_hc(const float* __restrict__ hw, const float* __restrict__ hb,
                        const float* __restrict__ cw, const float* __restrict__ cb) {
    int b = blockIdx.x, tid = threadIdx.x;
    int lane = tid & 31, wid = tid >> 5;
    __shared__ float x[1280];
    for (int k = tid; k < 1280; k += 256) x[k] = g_inp0[b * 1280 + k];
    __syncthreads();
    for (int d = wid; d < Dz; d += 8) {
        float sh = 0.f, sc = 0.f;
        const float* hr = hw + (size_t)d * 1280;
        const float* cr = cw + (size_t)d * 1280;
        for (int k = lane; k < 1280; k += 32) { float xv = x[k]; sh += hr[k] * xv; sc += cr[k] * xv; }
#pragma unroll
        for (int o = 16; o; o >>= 1) {
            sh += __shfl_xor_sync(0xffffffffu, sh, o);
            sc += __shfl_xor_sync(0xffffffffu, sc, o);
        }
        if (!lane) { g_h[b * Dz + d] = sh + hb[d]; g_c[b * Dz + d] = sc + cb[d]; }
    }
}

// ---------------- embed all captions once ----------------
__global__ void embed_all(const float* __restrict__ emb, const int* __restrict__ captions) {
    int bs = blockIdx.x;          // b*Sz + t
    int cap = captions[bs];
    const float* e = emb + (size_t)cap * Ez;
    for (int k = threadIdx.x; k < Ez; k += 256) g_embs[(size_t)bs * Ez + k] = e[k];
}

// ---------------- SGEMM: C[M,N] = A[M,K] @ W[N,K]^T + bias ----------------
// BM=128 BN=128 BK=16, 256 threads, 8x8 per thread, register prefetch.
// M % 128 == 0, K % 16 == 0; N guarded.
template <bool PERM>
__global__ void __launch_bounds__(256, 2)
sgemm128x128(const float* __restrict__ A, const float* __restrict__ W,
             const float* __restrict__ bias, float* __restrict__ C,
             int M, int N, int K) {
    __shared__ float As[16][128];
    __shared__ float Bs[16][128];
    const int m0 = blockIdx.x * 128, n0 = blockIdx.y * 128;
    const int tid = threadIdx.x;
    const int tx = tid & 15, ty = tid >> 4;
    const int lr = tid >> 2, lc = (tid & 3) << 2;
    const float4 z4 = make_float4(0.f, 0.f, 0.f, 0.f);

    float4 a0, a1, b0, b1;
    a0 = *(const float4*)&A[(size_t)(m0 + lr) * K + lc];
    a1 = *(const float4*)&A[(size_t)(m0 + lr + 64) * K + lc];
    b0 = (n0 + lr < N) ? *(const float4*)&W[(size_t)(n0 + lr) * K + lc] : z4;
    b1 = (n0 + lr + 64 < N) ? *(const float4*)&W[(size_t)(n0 + lr + 64) * K + lc] : z4;

    float acc[8][8] = {};
    for (int k0 = 0; k0 < K; k0 += 16) {
        As[lc + 0][lr] = a0.x; As[lc + 1][lr] = a0.y; As[lc + 2][lr] = a0.z; As[lc + 3][lr] = a0.w;
        As[lc + 0][lr + 64] = a1.x; As[lc + 1][lr + 64] = a1.y; As[lc + 2][lr + 64] = a1.z; As[lc + 3][lr + 64] = a1.w;
        Bs[lc + 0][lr] = b0.x; Bs[lc + 1][lr] = b0.y; Bs[lc + 2][lr] = b0.z; Bs[lc + 3][lr] = b0.w;
        Bs[lc + 0][lr + 64] = b1.x; Bs[lc + 1][lr + 64] = b1.y; Bs[lc + 2][lr + 64] = b1.z; Bs[lc + 3][lr + 64] = b1.w;
        __syncthreads();
        if (k0 + 16 < K) {
            int kn = k0 + 16;
            a0 = *(const float4*)&A[(size_t)(m0 + lr) * K + kn + lc];
            a1 = *(const float4*)&A[(size_t)(m0 + lr + 64) * K + kn + lc];
            b0 = (n0 + lr < N) ? *(const float4*)&W[(size_t)(n0 + lr) * K + kn + lc] : z4;
            b1 = (n0 + lr + 64 < N) ? *(const float4*)&W[(size_t)(n0 + lr + 64) * K + kn + lc] : z4;
        }
#pragma unroll
        for (int k = 0; k < 16; k++) {
            float ra[8], rb[8];
            *(float4*)&ra[0] = *(const float4*)&As[k][ty * 8];
            *(float4*)&ra[4] = *(const float4*)&As[k][ty * 8 + 4];
            *(float4*)&rb[0] = *(const float4*)&Bs[k][tx * 8];
            *(float4*)&rb[4] = *(const float4*)&Bs[k][tx * 8 + 4];
#pragma unroll
            for (int i = 0; i < 8; i++)
#pragma unroll
                for (int j = 0; j < 8; j++) acc[i][j] += ra[i] * rb[j];
        }
        __syncthreads();
    }
#pragma unroll
    for (int i = 0; i < 8; i++) {
        int m = m0 + ty * 8 + i;
#pragma unroll
        for (int j = 0; j < 8; j++) {
            int n = n0 + tx * 8 + j;
            if (n < N) {
                float v = acc[i][j] + bias[n];
                if (PERM) {
                    int bb = m & 63, tt = m >> 6;            // m = t*64 + b
                    C[(size_t)(bb * Sz + tt) * N + n] = v;   // preds[b][t][v]
                } else {
                    C[(size_t)m * N + n] = v;
                }
            }
        }
    }
}

// ---------------- fused attention (one block per (type, batch)) ----------------
__global__ void attend_kernel(const float* __restrict__ features, const float* __restrict__ articles,
                              const float* __restrict__ attWw, const float* __restrict__ attWb,
                              const float* __restrict__ attAw, const float* __restrict__ attAb,
                              const float* __restrict__ paWw, const float* __restrict__ paWb,
                              const float* __restrict__ paAw, const float* __restrict__ paAb,
                              float* __restrict__ out, int t) {
    const int type = blockIdx.x, b = blockIdx.y;
    const int tid = threadIdx.x, lane = tid & 31, wid = tid >> 5;
    __shared__ float hsh[512], wah[512], sc[200];
    __shared__ float red[8];
    __shared__ float s_max, s_sum;

    const float* Ww = type ? paWw : attWw;
    const float* Wb = type ? paWb : attWb;
    const float* Aw = type ? paAw : attAw;
    const float  Ab = (type ? paAb : attAb)[0];
    const float* u  = type ? (g_u_art + (size_t)b * NP * Az) : (g_u_feat + (size_t)b * NF * Az);
    const float* F  = type ? (articles + (size_t)b * NP * BENC) : (features + (size_t)b * NF * ENC);
    const int Nn = type ? NP : NF;
    const int Kd = type ? BENC : ENC;
    float* ctxp = type ? (g_pctx + b * BENC) : (g_ctx + b * ENC);

    hsh[tid] = g_h[b * Dz + tid];
    hsh[tid + 256] = g_h[b * Dz + tid + 256];
    __syncthreads();

    // w_ah = h @ Ww^T + Wb
    for (int a = wid; a < Az; a += 8) {
        float s = 0.f;
        const float* wr_ = Ww + (size_t)a * Dz;
        for (int k = lane; k < Dz; k += 32) s += wr_[k] * hsh[k];
        s = wred(s);
        if (!lane) wah[a] = s + Wb[a];
    }
    __syncthreads();

    // scores[n] = tanh(u[n] + w_ah) . Aw + Ab   (MUFU tanh)
    for (int n = wid; n < Nn; n += 8) {
        const float* ur = u + (size_t)n * Az;
        float s = 0.f;
        for (int a = lane; a < Az; a += 32) s += tanha(ur[a] + wah[a]) * Aw[a];
        s = wred(s);
        if (!lane) sc[n] = s + Ab;
    }
    __syncthreads();

    // softmax over n
    float m = -1e30f;
    for (int n = tid; n < Nn; n += 256) m = fmaxf(m, sc[n]);
#pragma unroll
    for (int o = 16; o; o >>= 1) m = fmaxf(m, __shfl_xor_sync(0xffffffffu, m, o));
    if (!lane) red[wid] = m;
    __syncthreads();
    if (tid == 0) {
        float mm = red[0];
        for (int i = 1; i < 8; i++) mm = fmaxf(mm, red[i]);
        s_max = mm;
    }
    __syncthreads();
    float e = 0.f;
    for (int n = tid; n < Nn; n += 256) { float ex = expf(sc[n] - s_max); sc[n] = ex; e += ex; }
    e = wred(e);
    if (!lane) red[wid] = e;
    __syncthreads();
    if (tid == 0) {
        float ss = 0.f;
        for (int i = 0; i < 8; i++) ss += red[i];
        s_sum = ss;
    }
    __syncthreads();
    const float inv = 1.f / s_sum;
    size_t obase = type ? ((size_t)OFF_PA + (size_t)(b * Sz + t) * NP)
                        : ((size_t)OFF_ALPHA + (size_t)(b * Sz + t) * NF);
    for (int n = tid; n < Nn; n += 256) { float al = sc[n] * inv; sc[n] = al; out[obase + n] = al; }
    __syncthreads();

    // ctx = alpha @ F
    for (int k = tid; k < Kd; k += 256) {
        float acc = 0.f;
        for (int n = 0; n < Nn; n++) acc += sc[n] * F[(size_t)n * Kd + k];
        ctxp[k] = acc;
    }
}

// ---------------- LSTM gates GEMM, split by x-segment ----------------
// grid (64 n-blocks of 32, 4 segments), 256 threads
__global__ void gates_gemm(const float* __restrict__ w_ih, const float* __restrict__ w_hh, int t) {
    __shared__ float Xs[16][64];
    __shared__ float Ws[16][32];
    const int n0 = blockIdx.x * 32;
    const int s  = blockIdx.y;
    const int tid = threadIdx.x;
    const int tx = tid % 8, ty = tid / 8;   // ty*2 rows (batch), tx*4 cols
    const int xr = tid / 4, xc = (tid % 4) * 4;

    const float* xs;
    int Ks, kofs;
    if (s == 0)      { xs = g_embs + ((size_t)xr * Sz + t) * Ez; Ks = 512; kofs = 0; }
    else if (s == 1) { xs = g_ctx + xr * ENC;  Ks = 512; kofs = 512; }
    else if (s == 2) { xs = g_pctx + xr * BENC; Ks = 768; kofs = 1024; }
    else             { xs = g_h + xr * Dz;     Ks = 512; kofs = 0; }   // w_hh

    const int iters = Ks / 16;
    float acc[2][4] = {};
    for (int it = 0; it < iters; it++) {
        int kl = it * 16;
        float4 xv = *(const float4*)&xs[kl + xc];
        float4 wv = make_float4(0.f, 0.f, 0.f, 0.f);
        if (tid < 128) {
            int j = n0 + tid / 4;
            int kg = kl + (tid % 4) * 4;
            const float* src = (s == 3) ? &w_hh[(size_t)j * 512 + kg]
                                        : &w_ih[(size_t)j * 1792 + kofs + kg];
            wv = *(const float4*)src;
        }
        __syncthreads();
        Xs[xc + 0][xr] = xv.x; Xs[xc + 1][xr] = xv.y; Xs[xc + 2][xr] = xv.z; Xs[xc + 3][xr] = xv.w;
        if (tid < 128) {
            int n = tid / 4, kq = (tid % 4) * 4;
            Ws[kq + 0][n] = wv.x; Ws[kq + 1][n] = wv.y; Ws[kq + 2][n] = wv.z; Ws[kq + 3][n] = wv.w;
        }
        __syncthreads();
#pragma unroll
        for (int k = 0; k < 16; k++) {
            float ra0 = Xs[k][ty * 2], ra1 = Xs[k][ty * 2 + 1];
            float rb[4];
            *(float4*)&rb[0] = *(const float4*)&Ws[k][tx * 4];
#pragma unroll
            for (int j = 0; j < 4; j++) { acc[0][j] += ra0 * rb[j]; acc[1][j] += ra1 * rb[j]; }
        }
        __syncthreads();
    }
#pragma unroll
    for (int i = 0; i < 2; i++) {
        int b = ty * 2 + i;
#pragma unroll
        for (int j = 0; j < 4; j++) {
            int n = n0 + tx * 4 + j;
            g_gparts[((size_t)s * Bz + b) * G4 + n] = acc[i][j];
        }
    }
}

// ---------------- LSTM pointwise update ----------------
__global__ void lstm_update(const float* __restrict__ b_ih, const float* __restrict__ b_hh, int t) {
    int b = blockIdx.x, tid = threadIdx.x;
    for (int d = tid; d < Dz; d += 256) {
        float gi = b_ih[d] + b_hh[d];
        float gf = b_ih[512 + d] + b_hh[512 + d];
        float gg = b_ih[1024 + d] + b_hh[1024 + d];
        float go = b_ih[1536 + d] + b_hh[1536 + d];
#pragma unroll
        for (int ks = 0; ks < 4; ks++) {
            const float* gp = g_gparts + ((size_t)ks * Bz + b) * G4;
            gi += gp[d]; gf += gp[512 + d]; gg += gp[1024 + d]; go += gp[1536 + d];
        }
        float cp = g_c[b * Dz + d];
        float cn = sigm(gf) * cp + sigm(gi) * tanhf(gg);
        float hn = sigm(go) * tanhf(cn);
        g_c[b * Dz + d] = cn;
        g_h[b * Dz + d] = hn;
        g_hall[((size_t)t * Bz + b) * Dz + d] = hn;
    }
}

// ---------------- launcher ----------------
extern "C" void kernel_launch(void* const* d_in, const int* in_sizes, int n_in,
                              void* d_out, int out_size) {
    const float* features = (const float*)d_in[0];
    const float* articles = (const float*)d_in[1];
    const int*   captions = (const int*)d_in[2];
    const float* emb      = (const float*)d_in[3];
    const float* att_W_w  = (const float*)d_in[4];
    const float* att_W_b  = (const float*)d_in[5];
    const float* att_U_w  = (const float*)d_in[6];
    const float* att_U_b  = (const float*)d_in[7];
    const float* att_A_w  = (const float*)d_in[8];
    const float* att_A_b  = (const float*)d_in[9];
    const float* pa_W_w   = (const float*)d_in[10];
    const float* pa_W_b   = (const float*)d_in[11];
    const float* pa_U_w   = (const float*)d_in[12];
    const float* pa_U_b   = (const float*)d_in[13];
    const float* pa_A_w   = (const float*)d_in[14];
    const float* pa_A_b   = (const float*)d_in[15];
    const float* init_h_w = (const float*)d_in[16];
    const float* init_h_b = (const float*)d_in[17];
    const float* init_c_w = (const float*)d_in[18];
    const float* init_c_b = (const float*)d_in[19];
    const float* lstm_w_ih = (const float*)d_in[20];
    const float* lstm_w_hh = (const float*)d_in[21];
    const float* lstm_b_ih = (const float*)d_in[22];
    const float* lstm_b_hh = (const float*)d_in[23];
    const float* fcn_w    = (const float*)d_in[24];
    const float* fcn_b    = (const float*)d_in[25];
    float* out = (float*)d_out;

    float *p_uf, *p_ua, *p_hall;
    cudaGetSymbolAddress((void**)&p_uf, g_u_feat);
    cudaGetSymbolAddress((void**)&p_ua, g_u_art);
    cudaGetSymbolAddress((void**)&p_hall, g_hall);

    mean_kernel<<<Bz, 256>>>(features, articles);
    init_hc<<<Bz, 256>>>(init_h_w, init_h_b, init_c_w, init_c_b);
    embed_all<<<Bz * Sz, 256>>>(emb, captions);

    // u_feat = features @ att_U_w^T + b : [12544,512]
    sgemm128x128<false><<<dim3(98, 4), 256>>>(features, att_U_w, att_U_b, p_uf, Bz * NF, Az, ENC);
    // u_art = articles @ pa_U_w^T + b : [4096,512]
    sgemm128x128<false><<<dim3(32, 4), 256>>>(articles, pa_U_w, pa_U_b, p_ua, Bz * NP, Az, BENC);

    for (int t = 0; t < Sz; t++) {
        attend_kernel<<<dim3(2, Bz), 256>>>(features, articles,
                                            att_W_w, att_W_b, att_A_w, att_A_b,
                                            pa_W_w, pa_W_b, pa_A_w, pa_A_b, out, t);
        gates_gemm<<<dim3(64, 4), 256>>>(lstm_w_ih, lstm_w_hh, t);
        lstm_update<<<Bz, 256>>>(lstm_b_ih, lstm_b_hh, t);
    }

    // preds: [2048,512] @ [30000,512]^T, permuted store into [B,S,V]
    sgemm128x128<true><<<dim3(16, 235), 256>>>(p_hall, fcn_w, fcn_b, out, Sz * Bz, Vz, Dz);
}

// round 6
// speedup vs baseline: 1.5540x; 1.2029x over previous
#include <cuda_runtime.h>
#include <cuda_bf16.h>
#include <math.h>
#include <stdint.h>

#define Bz   64
#define Sz   32
#define NF   196
#define NP   64
#define ENC  512
#define BENC 768
#define Az   512
#define Dz   512
#define Ez   512
#define Vz   30000
#define G4   2048
#define VPAD 30208
#define NBLK 128

#define OFF_ALPHA  61440000u
#define OFF_PA     61841408u

// ---------------- scratch ----------------
__device__ float g_inp0[Bz * 1280];
__device__ float g_u_feat[Bz * NF * Az];
__device__ float g_u_art [Bz * NP * Az];
__device__ float g_h[Bz * Dz], g_c[Bz * Dz];
__device__ float g_ctx[Bz * ENC], g_pctx[Bz * BENC];
__device__ float g_embs[Bz * Sz * Ez];
__device__ float g_gparts[4 * Bz * G4];

__device__ __nv_bfloat16 g_fhi[Bz * NF * ENC],  g_flo[Bz * NF * ENC];
__device__ __nv_bfloat16 g_arhi[Bz * NP * BENC], g_arlo[Bz * NP * BENC];
__device__ __nv_bfloat16 g_w1hi[Az * ENC],  g_w1lo[Az * ENC];
__device__ __nv_bfloat16 g_w2hi[Az * BENC], g_w2lo[Az * BENC];
__device__ __nv_bfloat16 g_whi[(size_t)VPAD * Dz], g_wlo[(size_t)VPAD * Dz];
__device__ __nv_bfloat16 g_ahi[Sz * Bz * Dz], g_alo[Sz * Bz * Dz];

// global barrier state
__device__ unsigned g_cnt;
__device__ volatile unsigned g_gen;

__device__ __forceinline__ float wred(float v) {
#pragma unroll
    for (int o = 16; o; o >>= 1) v += __shfl_xor_sync(0xffffffffu, v, o);
    return v;
}
__device__ __forceinline__ float sigm(float x) { return 1.f / (1.f + expf(-x)); }
__device__ __forceinline__ float tanha(float x) {
    float y; asm("tanh.approx.f32 %0, %1;" : "=f"(y) : "f"(x)); return y;
}
__device__ __forceinline__ uint32_t smem_u32(const void* p) {
    uint32_t a;
    asm("{ .reg .u64 t; cvta.to.shared.u64 t, %1; cvt.u32.u64 %0, t; }" : "=r"(a) : "l"(p));
    return a;
}
__device__ __forceinline__ uint32_t lds32(uint32_t a) {
    uint32_t v; asm volatile("ld.shared.b32 %0, [%1];" : "=r"(v) : "r"(a)); return v;
}
__device__ __forceinline__ void mma16816(float* c, uint32_t a0, uint32_t a1, uint32_t a2,
                                         uint32_t a3, uint32_t b0, uint32_t b1) {
    asm volatile("mma.sync.aligned.m16n8k16.row.col.f32.bf16.bf16.f32 "
                 "{%0,%1,%2,%3}, {%4,%5,%6,%7}, {%8,%9}, {%0,%1,%2,%3};"
                 : "+f"(c[0]), "+f"(c[1]), "+f"(c[2]), "+f"(c[3])
                 : "r"(a0), "r"(a1), "r"(a2), "r"(a3), "r"(b0), "r"(b1));
}
// swizzled smem offset: 128 rows x 32 bf16 (64B rows), 16B slots
__device__ __forceinline__ uint32_t swz(int r, int slot) {
    return (uint32_t)(r * 64 + ((slot ^ ((r >> 1) & 3)) << 4));
}

__device__ __forceinline__ void gbar() {
    __threadfence();
    __syncthreads();
    if (threadIdx.x == 0) {
        unsigned gen = g_gen;
        if (atomicAdd(&g_cnt, 1u) == NBLK - 1) {
            g_cnt = 0;
            __threadfence();
            g_gen = gen + 1;
        } else {
            while (g_gen == gen) {}
        }
    }
    __syncthreads();
}

// -------- fp32 -> split bf16 --------
__global__ void conv_split(const float* __restrict__ src, __nv_bfloat16* __restrict__ hi,
                           __nv_bfloat16* __restrict__ lo, int n_src, int n_pad) {
    int i = (blockIdx.x * 256 + threadIdx.x) * 4;
    if (i >= n_pad) return;
    float4 v = make_float4(0.f, 0.f, 0.f, 0.f);
    if (i < n_src) v = *(const float4*)(src + i);
    __nv_bfloat16 h0 = __float2bfloat16(v.x), h1 = __float2bfloat16(v.y);
    __nv_bfloat16 h2 = __float2bfloat16(v.z), h3 = __float2bfloat16(v.w);
    ((__nv_bfloat162*)(hi + i))[0] = __halves2bfloat162(h0, h1);
    ((__nv_bfloat162*)(hi + i))[1] = __halves2bfloat162(h2, h3);
    ((__nv_bfloat162*)(lo + i))[0] = __halves2bfloat162(
        __float2bfloat16(v.x - __bfloat162float(h0)), __float2bfloat16(v.y - __bfloat162float(h1)));
    ((__nv_bfloat162*)(lo + i))[1] = __halves2bfloat162(
        __float2bfloat16(v.z - __bfloat162float(h2)), __float2bfloat16(v.w - __bfloat162float(h3)));
}

// -------- split-bf16 mma.sync GEMM: C[M,N] = A@W^T + bias --------
// tile 128x128, BK=32, K' = 3K (hi*hi, lo*hi, hi*lo). grid(ntiles, mtiles).
template <bool PERM>
__global__ void __launch_bounds__(256)
gemm_mma(const __nv_bfloat16* __restrict__ Ahi, const __nv_bfloat16* __restrict__ Alo,
         const __nv_bfloat16* __restrict__ Whi, const __nv_bfloat16* __restrict__ Wlo,
         const float* __restrict__ bias, float* __restrict__ C, int N, int K) {
    __shared__ __align__(16) char smA[8192];
    __shared__ __align__(16) char smW[8192];
    const int tid = threadIdx.x, lane = tid & 31, wid = tid >> 5;
    const int wm = wid & 1, wn = wid >> 1;
    const int lr4 = lane >> 2, lw = lane & 3;
    const int n0 = blockIdx.x * 128, m0 = blockIdx.y * 128;
    const uint32_t sa = smem_u32(smA), sw = smem_u32(smW);
    const int kc = K >> 5, nch = 3 * kc;

    // per-thread load slots: A/W each 512 slots of 16B
    const int r1 = tid >> 2, cA = tid & 3;    // rows r1 and r1+64
    const uint32_t so1 = swz(r1, cA), so2 = swz(r1 + 64, cA);

    float acc[4][4][4] = {};
    int4 pa0, pa1, pw0, pw1;
    {
        const __nv_bfloat16* As = Ahi;  // chunk 0: part 0
        const __nv_bfloat16* Ws = Whi;
        pa0 = *(const int4*)(As + (size_t)(m0 + r1) * K + cA * 8);
        pa1 = *(const int4*)(As + (size_t)(m0 + r1 + 64) * K + cA * 8);
        pw0 = *(const int4*)(Ws + (size_t)(n0 + r1) * K + cA * 8);
        pw1 = *(const int4*)(Ws + (size_t)(n0 + r1 + 64) * K + cA * 8);
    }

    for (int cc = 0; cc < nch; cc++) {
        *(int4*)(smA + so1) = pa0;
        *(int4*)(smA + so2) = pa1;
        *(int4*)(smW + so1) = pw0;
        *(int4*)(smW + so2) = pw1;
        __syncthreads();
        if (cc + 1 < nch) {
            int nx = cc + 1;
            int part = (nx >= 2 * kc) ? 2 : (nx >= kc ? 1 : 0);
            int kk = (nx - part * kc) << 5;
            const __nv_bfloat16* As = (part == 1) ? Alo : Ahi;
            const __nv_bfloat16* Ws = (part == 2) ? Wlo : Whi;
            pa0 = *(const int4*)(As + (size_t)(m0 + r1) * K + kk + cA * 8);
            pa1 = *(const int4*)(As + (size_t)(m0 + r1 + 64) * K + kk + cA * 8);
            pw0 = *(const int4*)(Ws + (size_t)(n0 + r1) * K + kk + cA * 8);
            pw1 = *(const int4*)(Ws + (size_t)(n0 + r1 + 64) * K + kk + cA * 8);
        }
#pragma unroll
        for (int ks = 0; ks < 2; ks++) {
            uint32_t bf[4][2];
#pragma unroll
            for (int ni = 0; ni < 4; ni++) {
                int nb = wn * 32 + ni * 8 + lr4;
                bf[ni][0] = lds32(sw + swz(nb, 2 * ks) + lw * 4);
                bf[ni][1] = lds32(sw + swz(nb, 2 * ks + 1) + lw * 4);
            }
#pragma unroll
            for (int mi = 0; mi < 4; mi++) {
                int ra = wm * 64 + mi * 16 + lr4, rb = ra + 8;
                uint32_t a0 = lds32(sa + swz(ra, 2 * ks) + lw * 4);
                uint32_t a1 = lds32(sa + swz(rb, 2 * ks) + lw * 4);
                uint32_t a2 = lds32(sa + swz(ra, 2 * ks + 1) + lw * 4);
                uint32_t a3 = lds32(sa + swz(rb, 2 * ks + 1) + lw * 4);
#pragma unroll
                for (int ni = 0; ni < 4; ni++)
                    mma16816(acc[mi][ni], a0, a1, a2, a3, bf[ni][0], bf[ni][1]);
            }
        }
        __syncthreads();
    }

#pragma unroll
    for (int mi = 0; mi < 4; mi++) {
#pragma unroll
        for (int ni = 0; ni < 4; ni++) {
            int m = m0 + wm * 64 + mi * 16 + lr4;
            int n = n0 + wn * 32 + ni * 8 + lw * 2;
            if (n < N) {
                float bx = bias[n], by = bias[n + 1];
                size_t row0 = PERM ? (size_t)((m & 63) * Sz + (m >> 6)) * N : (size_t)m * N;
                size_t row1 = PERM ? (size_t)(((m + 8) & 63) * Sz + ((m + 8) >> 6)) * N
                                   : (size_t)(m + 8) * N;
                float2 v0 = make_float2(acc[mi][ni][0] + bx, acc[mi][ni][1] + by);
                float2 v1 = make_float2(acc[mi][ni][2] + bx, acc[mi][ni][3] + by);
                *(float2*)(C + row0 + n) = v0;
                *(float2*)(C + row1 + n) = v1;
            }
        }
    }
}

// ---------------- prologue kernels ----------------
__global__ void mean_kernel(const float* __restrict__ features, const float* __restrict__ articles) {
    int b = blockIdx.x, tid = threadIdx.x;
    for (int k = tid; k < ENC; k += 256) {
        float s = 0.f;
        const float* p = features + (size_t)b * NF * ENC + k;
        for (int n = 0; n < NF; n++) s += p[n * ENC];
        g_inp0[b * 1280 + k] = s * (1.f / NF);
    }
    for (int k = tid; k < BENC; k += 256) {
        float s = 0.f;
        const float* p = articles + (size_t)b * NP * BENC + k;
        for (int n = 0; n < NP; n++) s += p[n * BENC];
        g_inp0[b * 1280 + ENC + k] = s * (1.f / NP);
    }
}

__global__ void init_hc(const float* __restrict__ hw, const float* __restrict__ hb,
                        const float* __restrict__ cw, const float* __restrict__ cb) {
    int b = blockIdx.x, tid = threadIdx.x;
    int lane = tid & 31, wid = tid >> 5;
    __shared__ float x[1280];
    for (int k = tid; k < 1280; k += 256) x[k] = g_inp0[b * 1280 + k];
    __syncthreads();
    for (int d = wid; d < Dz; d += 8) {
        float sh = 0.f, sc = 0.f;
        const float* hr = hw + (size_t)d * 1280;
        const float* cr = cw + (size_t)d * 1280;
        for (int k = lane; k < 1280; k += 32) { float xv = x[k]; sh += hr[k] * xv; sc += cr[k] * xv; }
#pragma unroll
        for (int o = 16; o; o >>= 1) {
            sh += __shfl_xor_sync(0xffffffffu, sh, o);
            sc += __shfl_xor_sync(0xffffffffu, sc, o);
        }
        if (!lane) { g_h[b * Dz + d] = sh + hb[d]; g_c[b * Dz + d] = sc + cb[d]; }
    }
}

__global__ void embed_all(const float* __restrict__ emb, const int* __restrict__ captions) {
    int bs = blockIdx.x;
    int cap = captions[bs];
    const float* e = emb + (size_t)cap * Ez;
    for (int k = threadIdx.x; k < Ez; k += 256) g_embs[(size_t)bs * Ez + k] = e[k];
}

// ---------------- persistent recurrent loop ----------------
__device__ __forceinline__ void attend_p(float* sh, const float* F, const float* u,
                                         const float* Ww, const float* Wb,
                                         const float* Aw, float Ab,
                                         int b, int Nn, int Kd, float* ctxp,
                                         float* outp) {
    const int tid = threadIdx.x, lane = tid & 31, wid = tid >> 5;
    float* hsh = sh;          // 512
    float* wah = sh + 512;    // 512
    float* sc  = sh + 1024;   // 200
    float* red = sh + 1232;   // 8
    float* sm  = sh + 1240;   // 2

    hsh[tid] = g_h[b * Dz + tid];
    hsh[tid + 256] = g_h[b * Dz + tid + 256];
    __syncthreads();

    for (int a = wid; a < Az; a += 8) {
        float s = 0.f;
        const float* wr_ = Ww + (size_t)a * Dz;
        for (int k = lane; k < Dz; k += 32) s += wr_[k] * hsh[k];
        s = wred(s);
        if (!lane) wah[a] = s + Wb[a];
    }
    __syncthreads();

    for (int n = wid; n < Nn; n += 8) {
        const float* ur = u + (size_t)n * Az;
        float s = 0.f;
        for (int a = lane; a < Az; a += 32) s += tanha(ur[a] + wah[a]) * Aw[a];
        s = wred(s);
        if (!lane) sc[n] = s + Ab;
    }
    __syncthreads();

    float m = -1e30f;
    for (int n = tid; n < Nn; n += 256) m = fmaxf(m, sc[n]);
#pragma unroll
    for (int o = 16; o; o >>= 1) m = fmaxf(m, __shfl_xor_sync(0xffffffffu, m, o));
    if (!lane) red[wid] = m;
    __syncthreads();
    if (tid == 0) {
        float mm = red[0];
        for (int i = 1; i < 8; i++) mm = fmaxf(mm, red[i]);
        sm[0] = mm;
    }
    __syncthreads();
    float e = 0.f;
    for (int n = tid; n < Nn; n += 256) { float ex = expf(sc[n] - sm[0]); sc[n] = ex; e += ex; }
    e = wred(e);
    if (!lane) red[wid] = e;
    __syncthreads();
    if (tid == 0) {
        float ss = 0.f;
        for (int i = 0; i < 8; i++) ss += red[i];
        sm[1] = ss;
    }
    __syncthreads();
    const float inv = 1.f / sm[1];
    for (int n = tid; n < Nn; n += 256) { float al = sc[n] * inv; sc[n] = al; outp[n] = al; }
    __syncthreads();

    for (int k = tid; k < Kd; k += 256) {
        float acc = 0.f;
        for (int n = 0; n < Nn; n++) acc += sc[n] * F[(size_t)n * Kd + k];
        ctxp[k] = acc;
    }
}

__device__ __forceinline__ void gates_p(float* sh, const float* __restrict__ w_ih,
                                        const float* __restrict__ w_hh, int s, int n0, int t) {
    float* Xs = sh;            // [16][64]
    float* Ws = sh + 1024;     // [16][32]
    const int tid = threadIdx.x;
    const int tx = tid % 8, ty = tid / 8;
    const int xr = tid / 4, xc = (tid % 4) * 4;

    const float* xs;
    int Ks, kofs;
    if (s == 0)      { xs = g_embs + ((size_t)xr * Sz + t) * Ez; Ks = 512; kofs = 0; }
    else if (s == 1) { xs = g_ctx + xr * ENC;   Ks = 512; kofs = 512; }
    else if (s == 2) { xs = g_pctx + xr * BENC; Ks = 768; kofs = 1024; }
    else             { xs = g_h + xr * Dz;      Ks = 512; kofs = 0; }

    const int iters = Ks / 16;
    float acc[2][4] = {};
    __syncthreads();
    for (int it = 0; it < iters; it++) {
        int kl = it * 16;
        float4 xv = *(const float4*)&xs[kl + xc];
        float4 wv = make_float4(0.f, 0.f, 0.f, 0.f);
        if (tid < 128) {
            int j = n0 + tid / 4;
            int kg = kl + (tid % 4) * 4;
            const float* src = (s == 3) ? &w_hh[(size_t)j * 512 + kg]
                                        : &w_ih[(size_t)j * 1792 + kofs + kg];
            wv = *(const float4*)src;
        }
        __syncthreads();
        Xs[(xc + 0) * 64 + xr] = xv.x; Xs[(xc + 1) * 64 + xr] = xv.y;
        Xs[(xc + 2) * 64 + xr] = xv.z; Xs[(xc + 3) * 64 + xr] = xv.w;
        if (tid < 128) {
            int n = tid / 4, kq = (tid % 4) * 4;
            Ws[(kq + 0) * 32 + n] = wv.x; Ws[(kq + 1) * 32 + n] = wv.y;
            Ws[(kq + 2) * 32 + n] = wv.z; Ws[(kq + 3) * 32 + n] = wv.w;
        }
        __syncthreads();
#pragma unroll
        for (int k = 0; k < 16; k++) {
            float ra0 = Xs[k * 64 + ty * 2], ra1 = Xs[k * 64 + ty * 2 + 1];
            float rb[4];
            *(float4*)&rb[0] = *(const float4*)&Ws[k * 32 + tx * 4];
#pragma unroll
            for (int j = 0; j < 4; j++) { acc[0][j] += ra0 * rb[j]; acc[1][j] += ra1 * rb[j]; }
        }
        __syncthreads();
    }
#pragma unroll
    for (int i = 0; i < 2; i++) {
        int b = ty * 2 + i;
#pragma unroll
        for (int j = 0; j < 4; j++)
            g_gparts[((size_t)s * Bz + b) * G4 + n0 + tx * 4 + j] = acc[i][j];
    }
}

__global__ void __launch_bounds__(256)
loop_kernel(const float* __restrict__ features, const float* __restrict__ articles,
            const float* __restrict__ attWw, const float* __restrict__ attWb,
            const float* __restrict__ attAw, const float* __restrict__ attAb,
            const float* __restrict__ paWw, const float* __restrict__ paWb,
            const float* __restrict__ paAw, const float* __restrict__ paAb,
            const float* __restrict__ w_ih, const float* __restrict__ w_hh,
            const float* __restrict__ b_ih, const float* __restrict__ b_hh,
            float* __restrict__ out) {
    __shared__ float sh[2048];
    const int bid = blockIdx.x, tid = threadIdx.x;
    const int type = bid >> 6, b = bid & 63;

    for (int t = 0; t < Sz; t++) {
        // Phase A: attend(type,b)  +  gates s0 (blocks 0-63) / s3 (blocks 64-127)
        if (type == 0) {
            attend_p(sh, features + (size_t)b * NF * ENC, g_u_feat + (size_t)b * NF * Az,
                     attWw, attWb, attAw, attAb[0], b, NF, ENC, g_ctx + b * ENC,
                     out + OFF_ALPHA + (size_t)(b * Sz + t) * NF);
        } else {
            attend_p(sh, articles + (size_t)b * NP * BENC, g_u_art + (size_t)b * NP * Az,
                     paWw, paWb, paAw, paAb[0], b, NP, BENC, g_pctx + b * BENC,
                     out + OFF_PA + (size_t)(b * Sz + t) * NP);
        }
        __syncthreads();
        gates_p(sh, w_ih, w_hh, type ? 3 : 0, b * 32, t);
        gbar();
        // Phase B: gates s1 / s2
        gates_p(sh, w_ih, w_hh, type ? 2 : 1, b * 32, t);
        gbar();
        // Phase C: LSTM pointwise (blocks 0-63)
        if (type == 0) {
            for (int d = tid; d < Dz; d += 256) {
                float gi = b_ih[d] + b_hh[d];
                float gf = b_ih[512 + d] + b_hh[512 + d];
                float gg = b_ih[1024 + d] + b_hh[1024 + d];
                float go = b_ih[1536 + d] + b_hh[1536 + d];
#pragma unroll
                for (int ks = 0; ks < 4; ks++) {
                    const float* gp = g_gparts + ((size_t)ks * Bz + b) * G4;
                    gi += gp[d]; gf += gp[512 + d]; gg += gp[1024 + d]; go += gp[1536 + d];
                }
                float cp = g_c[b * Dz + d];
                float cn = sigm(gf) * cp + sigm(gi) * tanhf(gg);
                float hn = sigm(go) * tanhf(cn);
                g_c[b * Dz + d] = cn;
                g_h[b * Dz + d] = hn;
                __nv_bfloat16 hh = __float2bfloat16(hn);
                __nv_bfloat16 hl = __float2bfloat16(hn - __bfloat162float(hh));
                size_t idx = ((size_t)t * Bz + b) * Dz + d;
                g_ahi[idx] = hh;
                g_alo[idx] = hl;
            }
        }
        gbar();
    }
}

// ---------------- launcher ----------------
extern "C" void kernel_launch(void* const* d_in, const int* in_sizes, int n_in,
                              void* d_out, int out_size) {
    const float* features = (const float*)d_in[0];
    const float* articles = (const float*)d_in[1];
    const int*   captions = (const int*)d_in[2];
    const float* emb      = (const float*)d_in[3];
    const float* att_W_w  = (const float*)d_in[4];
    const float* att_W_b  = (const float*)d_in[5];
    const float* att_U_w  = (const float*)d_in[6];
    const float* att_U_b  = (const float*)d_in[7];
    const float* att_A_w  = (const float*)d_in[8];
    const float* att_A_b  = (const float*)d_in[9];
    const float* pa_W_w   = (const float*)d_in[10];
    const float* pa_W_b   = (const float*)d_in[11];
    const float* pa_U_w   = (const float*)d_in[12];
    const float* pa_U_b   = (const float*)d_in[13];
    const float* pa_A_w   = (const float*)d_in[14];
    const float* pa_A_b   = (const float*)d_in[15];
    const float* init_h_w = (const float*)d_in[16];
    const float* init_h_b = (const float*)d_in[17];
    const float* init_c_w = (const float*)d_in[18];
    const float* init_c_b = (const float*)d_in[19];
    const float* lstm_w_ih = (const float*)d_in[20];
    const float* lstm_w_hh = (const float*)d_in[21];
    const float* lstm_b_ih = (const float*)d_in[22];
    const float* lstm_b_hh = (const float*)d_in[23];
    const float* fcn_w    = (const float*)d_in[24];
    const float* fcn_b    = (const float*)d_in[25];
    float* out = (float*)d_out;

    float *p_uf, *p_ua;
    cudaGetSymbolAddress((void**)&p_uf, g_u_feat);
    cudaGetSymbolAddress((void**)&p_ua, g_u_art);
    __nv_bfloat16 *fhi, *flo, *arhi, *arlo, *w1hi, *w1lo, *w2hi, *w2lo, *whi, *wlo, *ahi, *alo;
    cudaGetSymbolAddress((void**)&fhi, g_fhi);   cudaGetSymbolAddress((void**)&flo, g_flo);
    cudaGetSymbolAddress((void**)&arhi, g_arhi); cudaGetSymbolAddress((void**)&arlo, g_arlo);
    cudaGetSymbolAddress((void**)&w1hi, g_w1hi); cudaGetSymbolAddress((void**)&w1lo, g_w1lo);
    cudaGetSymbolAddress((void**)&w2hi, g_w2hi); cudaGetSymbolAddress((void**)&w2lo, g_w2lo);
    cudaGetSymbolAddress((void**)&whi, g_whi);   cudaGetSymbolAddress((void**)&wlo, g_wlo);
    cudaGetSymbolAddress((void**)&ahi, g_ahi);   cudaGetSymbolAddress((void**)&alo, g_alo);

    mean_kernel<<<Bz, 256>>>(features, articles);
    init_hc<<<Bz, 256>>>(init_h_w, init_h_b, init_c_w, init_c_b);
    embed_all<<<Bz * Sz, 256>>>(emb, captions);

    int nf = Bz * NF * ENC, na = Bz * NP * BENC;
    conv_split<<<(nf + 1023) / 1024, 256>>>(features, fhi, flo, nf, nf);
    conv_split<<<(na + 1023) / 1024, 256>>>(articles, arhi, arlo, na, na);
    conv_split<<<(Az * ENC + 1023) / 1024, 256>>>(att_U_w, w1hi, w1lo, Az * ENC, Az * ENC);
    conv_split<<<(Az * BENC + 1023) / 1024, 256>>>(pa_U_w, w2hi, w2lo, Az * BENC, Az * BENC);
    int nw = Vz * Dz, nwp = VPAD * Dz;
    conv_split<<<(nwp + 1023) / 1024, 256>>>(fcn_w, whi, wlo, nw, nwp);

    // u_feat: [12544,512] K=512 ; u_art: [4096,512] K=768
    gemm_mma<false><<<dim3(4, 98), 256>>>(fhi, flo, w1hi, w1lo, att_U_b, p_uf, Az, ENC);
    gemm_mma<false><<<dim3(4, 32), 256>>>(arhi, arlo, w2hi, w2lo, pa_U_b, p_ua, Az, BENC);

    // the whole 32-step recurrence in one persistent launch
    loop_kernel<<<NBLK, 256>>>(features, articles,
                               att_W_w, att_W_b, att_A_w, att_A_b,
                               pa_W_w, pa_W_b, pa_A_w, pa_A_b,
                               lstm_w_ih, lstm_w_hh, lstm_b_ih, lstm_b_hh, out);

    // fcn: [2048,512] @ [30000,512]^T -> permuted [B,S,V]
    gemm_mma<true><<<dim3(236, 16), 256>>>(ahi, alo, whi, wlo, fcn_b, out, Vz, Dz);
}